// round 4
// baseline (speedup 1.0000x reference)
#include <cuda_runtime.h>
#include <cuda_bf16.h>
#include <cstdint>

#define G    64
#define FOLD 256
#define HID  128
#define TM   128    // rows per tile
#define KC   32     // k per chunk
#define NCH  8      // chunks per tile (K=256)

// Scratch (device globals).
__device__ float g_num[3 * G * FOLD];
__device__ float g_den[3 * G];
__device__ __align__(16) __nv_bfloat16 g_w1bf[3 * FOLD * HID];

// Smem layout (bytes)
#define OFF_AS    0        // A tile: 128r x 32k bf16, interleaved -> 64 x 128B = 8192
#define OFF_BS    8192     // B ring: 4 x (32k x 128n bf16 = 8192)  = 32768
#define OFF_ACCS  40960    // 64 x 256 f32 = 65536
#define OFF_PART  106496   // 2 x 128 f32  = 1024
#define OFF_ES    107520   // 128 f32      = 512
#define OFF_SGS   108032   // 128 int      = 512
#define OFF_DENS  108544   // 64 f32       = 256
#define OFF_B1S   108800   // 128 f32      = 512
#define OFF_W2S   109312   // 128 f32      = 512
#define SMEM_SZ   109824

// ---------------------------------------------------------------------------
__global__ void prep_kernel(const float* __restrict__ pa,
                            const float* __restrict__ la,
                            const float* __restrict__ ca) {
    int i = blockIdx.x * blockDim.x + threadIdx.x;
    if (i < FOLD * HID) {
        g_w1bf[i]                = __float2bfloat16(pa[i]);
        g_w1bf[FOLD * HID + i]   = __float2bfloat16(la[i]);
        g_w1bf[2 * FOLD * HID + i] = __float2bfloat16(ca[i]);
    }
    if (i < 3 * G * FOLD) g_num[i] = 0.f;
    if (i < 3 * G)        g_den[i] = 0.f;
}

__device__ __forceinline__ uint32_t smem_u32(const void* p) {
    return (uint32_t)__cvta_generic_to_shared(p);
}
__device__ __forceinline__ uint32_t pack_bf16x2(float a, float b) {
    __nv_bfloat162 h = __floats2bfloat162_rn(a, b);
    return *reinterpret_cast<uint32_t*>(&h);
}

// ---------------------------------------------------------------------------
// Fused scores + attention-pool, pipelined.
__global__ __launch_bounds__(256, 2) void fused_kernel(
    const float* __restrict__ x, int N,
    const int* __restrict__ batch, const int* __restrict__ ci0,
    const int* __restrict__ lb, int indirect, int pool,
    const float* __restrict__ b1, const float* __restrict__ W2,
    const float* __restrict__ b2)
{
    extern __shared__ char smem[];
    char*  As   = smem + OFF_AS;
    char*  Bs   = smem + OFF_BS;
    float* accs = (float*)(smem + OFF_ACCS);
    float* part = (float*)(smem + OFF_PART);
    float* e_s  = (float*)(smem + OFF_ES);
    int*   sg_s = (int*)  (smem + OFF_SGS);
    float* dens = (float*)(smem + OFF_DENS);
    float* b1s  = (float*)(smem + OFF_B1S);
    float* w2s  = (float*)(smem + OFF_W2S);

    const __nv_bfloat16* W1b = g_w1bf + (size_t)pool * (FOLD * HID);

    const int tid    = threadIdx.x;
    const int lane   = tid & 31;
    const int warp   = tid >> 5;
    const int warp_m = warp >> 1;     // 0..3
    const int wn     = warp & 1;      // 0..1
    const int m0     = warp_m * 32;

    for (int i = tid; i < G * FOLD; i += 256) accs[i] = 0.f;
    if (tid < G) dens[tid] = 0.f;
    if (tid < HID) { b1s[tid] = b1[tid]; w2s[tid] = W2[tid]; }
    const float b2v = b2[0];
    __syncthreads();

    const uint32_t as_base = smem_u32(As);
    const uint32_t bs_base = smem_u32(Bs);
    const int ntiles = (N + TM - 1) / TM;

    for (int tile = blockIdx.x; tile < ntiles; tile += gridDim.x) {
        const int row0 = tile * TM;

        float acc[2][8][4];
#pragma unroll
        for (int mi = 0; mi < 2; mi++)
#pragma unroll
            for (int ni = 0; ni < 8; ni++)
#pragma unroll
                for (int j = 0; j < 4; j++) acc[mi][ni][j] = 0.f;

        float4 araw[4];
        // ---- prologue: A chunk 0 LDG + STS, B chunks 0..2 cp.async
#pragma unroll
        for (int jj = 0; jj < 2; jj++) {
            int idx2 = tid * 2 + jj;          // 0..511
            int r    = idx2 >> 2;
            int kc   = idx2 & 3;
            int grow = row0 + r;
            if (grow < N) {
                const float4* p = (const float4*)(x + (size_t)grow * FOLD + kc * 8);
                araw[2 * jj]     = p[0];
                araw[2 * jj + 1] = p[1];
            } else {
                araw[2 * jj]     = make_float4(0.f, 0.f, 0.f, 0.f);
                araw[2 * jj + 1] = make_float4(0.f, 0.f, 0.f, 0.f);
            }
        }
#pragma unroll
        for (int jj = 0; jj < 2; jj++) {
            int idx2 = tid * 2 + jj;
            int r    = idx2 >> 2;
            int kc   = idx2 & 3;
            uint4 v;
            v.x = pack_bf16x2(araw[2 * jj].x,     araw[2 * jj].y);
            v.y = pack_bf16x2(araw[2 * jj].z,     araw[2 * jj].w);
            v.z = pack_bf16x2(araw[2 * jj + 1].x, araw[2 * jj + 1].y);
            v.w = pack_bf16x2(araw[2 * jj + 1].z, araw[2 * jj + 1].w);
            int p  = r & 63;
            int c4 = kc + ((r >> 6) << 2);
            *(uint4*)(As + p * 128 + ((c4 ^ (p & 7)) << 4)) = v;
        }
#pragma unroll
        for (int i = 0; i < 3; i++) {
#pragma unroll
            for (int j = 0; j < 2; j++) {
                int idx = tid + j * 256;          // 0..511
                int k   = idx >> 4;
                int nc  = idx & 15;
                uint32_t dst = bs_base + (i & 3) * 8192 + k * 256 + ((nc ^ (k & 7)) << 4);
                const char* src = (const char*)W1b + (size_t)i * 8192 + (size_t)idx * 16;
                asm volatile("cp.async.cg.shared.global [%0], [%1], 16;"
                             :: "r"(dst), "l"(src));
            }
            asm volatile("cp.async.commit_group;");
        }

        // ---- main pipelined loop over 8 k-chunks
#pragma unroll 1
        for (int kt = 0; kt < NCH; kt++) {
            asm volatile("cp.async.wait_group 2;");
            __syncthreads();                 // A(kt) + B(kt) visible; bufs free

            if (kt < NCH - 1) {              // prefetch A(kt+1)
#pragma unroll
                for (int jj = 0; jj < 2; jj++) {
                    int idx2 = tid * 2 + jj;
                    int r    = idx2 >> 2;
                    int kc   = idx2 & 3;
                    int grow = row0 + r;
                    if (grow < N) {
                        const float4* p = (const float4*)(x + (size_t)grow * FOLD
                                                          + (kt + 1) * KC + kc * 8);
                        araw[2 * jj]     = p[0];
                        araw[2 * jj + 1] = p[1];
                    } else {
                        araw[2 * jj]     = make_float4(0.f, 0.f, 0.f, 0.f);
                        araw[2 * jj + 1] = make_float4(0.f, 0.f, 0.f, 0.f);
                    }
                }
            }
            if (kt < NCH - 3) {              // prefetch B(kt+3)
#pragma unroll
                for (int j = 0; j < 2; j++) {
                    int idx = tid + j * 256;
                    int k   = idx >> 4;
                    int nc  = idx & 15;
                    uint32_t dst = bs_base + ((kt + 3) & 3) * 8192
                                 + k * 256 + ((nc ^ (k & 7)) << 4);
                    const char* src = (const char*)W1b + (size_t)(kt + 3) * 8192
                                    + (size_t)idx * 16;
                    asm volatile("cp.async.cg.shared.global [%0], [%1], 16;"
                                 :: "r"(dst), "l"(src));
                }
            }
            asm volatile("cp.async.commit_group;");   // possibly-empty group

            const uint32_t bbuf = bs_base + (kt & 3) * 8192;
#pragma unroll
            for (int ks = 0; ks < 2; ks++) {
                uint32_t af[2][4];
#pragma unroll
                for (int mi = 0; mi < 2; mi++) {
                    int r  = m0 + mi * 16 + (lane & 7) + ((lane >> 3) & 1) * 8;
                    int kc = ks * 2 + (lane >> 4);
                    int p  = r & 63;
                    int c4 = kc + ((r >> 6) << 2);
                    uint32_t addr = as_base + p * 128 + ((c4 ^ (p & 7)) << 4);
                    asm volatile(
                        "ldmatrix.sync.aligned.m8n8.x4.shared.b16 {%0,%1,%2,%3}, [%4];"
                        : "=r"(af[mi][0]), "=r"(af[mi][1]), "=r"(af[mi][2]), "=r"(af[mi][3])
                        : "r"(addr));
                }
                uint32_t bf[8][2];
#pragma unroll
                for (int nj = 0; nj < 4; nj++) {
                    int k  = ks * 16 + (lane & 15);
                    int nc = wn * 8 + nj * 2 + (lane >> 4);
                    uint32_t addr = bbuf + k * 256 + ((nc ^ (k & 7)) << 4);
                    asm volatile(
                        "ldmatrix.sync.aligned.m8n8.x4.trans.shared.b16 {%0,%1,%2,%3}, [%4];"
                        : "=r"(bf[nj*2][0]), "=r"(bf[nj*2][1]),
                          "=r"(bf[nj*2+1][0]), "=r"(bf[nj*2+1][1])
                        : "r"(addr));
                }
#pragma unroll
                for (int mi = 0; mi < 2; mi++)
#pragma unroll
                    for (int ni = 0; ni < 8; ni++)
                        asm volatile(
                            "mma.sync.aligned.m16n8k16.row.col.f32.bf16.bf16.f32 "
                            "{%0,%1,%2,%3}, {%4,%5,%6,%7}, {%8,%9}, {%0,%1,%2,%3};"
                            : "+f"(acc[mi][ni][0]), "+f"(acc[mi][ni][1]),
                              "+f"(acc[mi][ni][2]), "+f"(acc[mi][ni][3])
                            : "r"(af[mi][0]), "r"(af[mi][1]), "r"(af[mi][2]), "r"(af[mi][3]),
                              "r"(bf[ni][0]), "r"(bf[ni][1]));
            }
            __syncthreads();                 // all warps done reading As

            if (kt < NCH - 1) {              // STS A(kt+1)
#pragma unroll
                for (int jj = 0; jj < 2; jj++) {
                    int idx2 = tid * 2 + jj;
                    int r    = idx2 >> 2;
                    int kc   = idx2 & 3;
                    uint4 v;
                    v.x = pack_bf16x2(araw[2 * jj].x,     araw[2 * jj].y);
                    v.y = pack_bf16x2(araw[2 * jj].z,     araw[2 * jj].w);
                    v.z = pack_bf16x2(araw[2 * jj + 1].x, araw[2 * jj + 1].y);
                    v.w = pack_bf16x2(araw[2 * jj + 1].z, araw[2 * jj + 1].w);
                    int p  = r & 63;
                    int c4 = kc + ((r >> 6) << 2);
                    *(uint4*)(As + p * 128 + ((c4 ^ (p & 7)) << 4)) = v;
                }
            }
        }

        // ---- epilogue: relu + 2nd linear, per-warp n64 partial per row
#pragma unroll
        for (int mi = 0; mi < 2; mi++) {
            float p1 = 0.f, p2 = 0.f;
            const int cb = (lane & 3) * 2;
#pragma unroll
            for (int ni = 0; ni < 8; ni++) {
                int c = wn * 64 + ni * 8 + cb;
                float w0 = w2s[c], w1v = w2s[c + 1];
                float q0 = b1s[c], q1 = b1s[c + 1];
                p1 += fmaxf(acc[mi][ni][0] + q0, 0.f) * w0 + fmaxf(acc[mi][ni][1] + q1, 0.f) * w1v;
                p2 += fmaxf(acc[mi][ni][2] + q0, 0.f) * w0 + fmaxf(acc[mi][ni][3] + q1, 0.f) * w1v;
            }
            p1 += __shfl_xor_sync(0xffffffffu, p1, 1);
            p1 += __shfl_xor_sync(0xffffffffu, p1, 2);
            p2 += __shfl_xor_sync(0xffffffffu, p2, 1);
            p2 += __shfl_xor_sync(0xffffffffu, p2, 2);
            if ((lane & 3) == 0) {
                int rl = m0 + mi * 16 + (lane >> 2);
                part[wn * 128 + rl]     = p1;
                part[wn * 128 + rl + 8] = p2;
            }
        }
        __syncthreads();

        if (tid < TM) {
            int row = row0 + tid;
            if (row < N) {
                float s = part[tid] + part[128 + tid] + b2v;
                e_s[tid]  = expf(s);
                sg_s[tid] = indirect ? __ldg(lb + __ldg(ci0 + row)) : __ldg(batch + row);
            } else {
                e_s[tid]  = 0.f;
                sg_s[tid] = 0;
            }
        }
        __syncthreads();

        if (tid < TM) atomicAdd(dens + sg_s[tid], e_s[tid]);

        // ---- pooling: thread owns column tid; register acc, flush on change
        const int rows = min(TM, N - row0);
        {
            const int c = tid;
            int   cur = sg_s[0];
            float a   = 0.f;
            int r = 0;
            for (; r + 4 <= rows; r += 4) {
                float xv[4];
#pragma unroll
                for (int j = 0; j < 4; j++)
                    xv[j] = __ldg(x + (size_t)(row0 + r + j) * FOLD + c);
#pragma unroll
                for (int j = 0; j < 4; j++) {
                    int   sg = sg_s[r + j];
                    float ev = e_s[r + j];
                    if (sg != cur) { accs[cur * FOLD + c] += a; a = 0.f; cur = sg; }
                    a = fmaf(ev, xv[j], a);
                }
            }
            for (; r < rows; ++r) {
                int   sg = sg_s[r];
                float ev = e_s[r];
                float xv = __ldg(x + (size_t)(row0 + r) * FOLD + c);
                if (sg != cur) { accs[cur * FOLD + c] += a; a = 0.f; cur = sg; }
                a = fmaf(ev, xv, a);
            }
            accs[cur * FOLD + c] += a;
        }
    }

    __syncthreads();
    float* num = g_num + pool * G * FOLD;
    for (int i = tid; i < G * FOLD; i += 256) {
        float v = accs[i];
        if (v != 0.f) atomicAdd(num + i, v);
    }
    if (tid < G && dens[tid] != 0.f) atomicAdd(g_den + pool * G + tid, dens[tid]);
}

// ---------------------------------------------------------------------------
__global__ __launch_bounds__(256) void mlp_kernel(
    const float* __restrict__ W1, const float* __restrict__ b1,
    const float* __restrict__ W2, const float* __restrict__ b2,
    const float* __restrict__ oW, const float* __restrict__ ob,
    float* __restrict__ out)
{
    __shared__ float comb[3 * FOLD];
    __shared__ float h1s[FOLD];
    __shared__ float h2s[HID];
    __shared__ float red[4];

    const int g = blockIdx.x, t = threadIdx.x;

    for (int i = t; i < 3 * FOLD; i += 256) {
        int p = i >> 8, cc = i & 255;
        comb[i] = g_num[(p * G + g) * FOLD + cc] / g_den[p * G + g];
    }
    __syncthreads();

    float h = b1[t];
    for (int k = 0; k < 3 * FOLD; k++)
        h = fmaf(comb[k], W1[(size_t)k * FOLD + t], h);
    h1s[t] = fmaxf(h, 0.f);
    __syncthreads();

    if (t < HID) {
        float h2 = b2[t];
        for (int k = 0; k < FOLD; k++)
            h2 = fmaf(h1s[k], W2[(size_t)k * HID + t], h2);
        h2s[t] = fmaxf(h2, 0.f);
    }
    __syncthreads();

    if (t < HID) {
        float v = h2s[t] * oW[t];
#pragma unroll
        for (int off = 16; off > 0; off >>= 1)
            v += __shfl_down_sync(0xffffffffu, v, off);
        if ((t & 31) == 0) red[t >> 5] = v;
    }
    __syncthreads();
    if (t == 0) out[g] = red[0] + red[1] + red[2] + red[3] + ob[0];
}

// ---------------------------------------------------------------------------
extern "C" void kernel_launch(void* const* d_in, const int* in_sizes, int n_in,
                              void* d_out, int out_size)
{
    const float* rec   = (const float*)d_in[0];
    const float* lig   = (const float*)d_in[1];
    const float* cross = (const float*)d_in[2];
    const int*   cidx  = (const int*)d_in[3];
    const int*   pb    = (const int*)d_in[4];
    const int*   lb    = (const int*)d_in[5];
    const float* paW1 = (const float*)d_in[7];
    const float* pab1 = (const float*)d_in[8];
    const float* paW2 = (const float*)d_in[9];
    const float* pab2 = (const float*)d_in[10];
    const float* laW1 = (const float*)d_in[11];
    const float* lab1 = (const float*)d_in[12];
    const float* laW2 = (const float*)d_in[13];
    const float* lab2 = (const float*)d_in[14];
    const float* caW1 = (const float*)d_in[15];
    const float* cab1 = (const float*)d_in[16];
    const float* caW2 = (const float*)d_in[17];
    const float* cab2 = (const float*)d_in[18];
    const float* mW1  = (const float*)d_in[19];
    const float* mb1  = (const float*)d_in[20];
    const float* mW2  = (const float*)d_in[21];
    const float* mb2  = (const float*)d_in[22];
    const float* oW   = (const float*)d_in[23];
    const float* ob   = (const float*)d_in[24];

    float* out = (float*)d_out;

    const int Np = in_sizes[0] / FOLD;
    const int Nl = in_sizes[1] / FOLD;
    const int Nc = in_sizes[2] / FOLD;

    static bool attr_done = false;
    if (!attr_done) {
        cudaFuncSetAttribute(fused_kernel,
                             cudaFuncAttributeMaxDynamicSharedMemorySize, SMEM_SZ);
        attr_done = true;
    }

    prep_kernel<<<(3 * G * FOLD + 255) / 256, 256>>>(paW1, laW1, caW1);

    const int maxb = 296;
    int gp = min((Np + TM - 1) / TM, maxb);
    int gl = min((Nl + TM - 1) / TM, maxb);
    int gc = min((Nc + TM - 1) / TM, maxb);

    fused_kernel<<<gp, 256, SMEM_SZ>>>(rec, Np, pb, nullptr, nullptr, 0, 0,
                                       pab1, paW2, pab2);
    fused_kernel<<<gl, 256, SMEM_SZ>>>(lig, Nl, lb, nullptr, nullptr, 0, 1,
                                       lab1, laW2, lab2);
    fused_kernel<<<gc, 256, SMEM_SZ>>>(cross, Nc, nullptr, cidx, lb, 1, 2,
                                       cab1, caW2, cab2);

    mlp_kernel<<<G, 256>>>(mW1, mb1, mW2, mb2, oW, ob, out);
}